// round 2
// baseline (speedup 1.0000x reference)
#include <cuda_runtime.h>
#include <math.h>

#define B_    64
#define T_    12
#define N_    800
#define CIN_  2
#define H_    64
#define HOR_  12
#define TC_IN 60
#define TC_H  2
#define MNUM_ 4
#define MDIM_ 8
#define IN0_  4
#define KAPPA_ 0.05f
#define NB    (N_*B_)      /* 51200 rows (node-major, batch inner) */

// ---------------- scratch (device globals; no allocs allowed) ----------------
__device__ float g_GT[N_*N_];                 // G transposed
__device__ float g_EMBX[B_*T_*N_*TC_H];       // encoder time-cov embedding
__device__ float g_EMBY[B_*HOR_*N_*TC_H];     // decoder time-cov embedding
__device__ float g_H0[NB*H_];                 // layer-0 hidden (N,B,H)
__device__ float g_H1[NB*H_];                 // layer-1 hidden
__device__ float g_F [NB*384];                // gate feature buffer [X|Y1|Y2]
__device__ float g_FC[NB*384];                // candidate feature buffer
__device__ float g_UR[NB*128];                // sigmoid(u|r)
__device__ float g_GO[NB*CIN_];               // decoder GO symbol
__device__ float g_Q [B_*MDIM_];
__device__ float g_ATTM[B_*N_*MDIM_];
__device__ float g_WG[4][384*128];            // folded gate weights: e0,e1,d0,d1
__device__ float g_WC[4][384*64];             // folded candidate weights

// ---------------- small utility kernels ----------------
__global__ void transpose_kernel(const float* __restrict__ G) {
    __shared__ float t[32][33];
    int x = blockIdx.x*32 + threadIdx.x, y = blockIdx.y*32 + threadIdx.y;
    t[threadIdx.y][threadIdx.x] = G[y*N_ + x];
    __syncthreads();
    int x2 = blockIdx.y*32 + threadIdx.x, y2 = blockIdx.x*32 + threadIdx.y;
    g_GT[y2*N_ + x2] = t[threadIdx.x][threadIdx.y];
}

// Fold kappa-mix into the k=0 block of the weights:
// W0' = W0 + k*(W1+W2);  W1' = (1-k)W1;  W2' = (1-k)W2   (row blocks of size P)
__global__ void fold_kernel(const float* __restrict__ W, int isGate, int widx, int P, int O) {
    float* Wf = isGate ? g_WG[widx] : g_WC[widx];
    int idx = blockIdx.x*256 + threadIdx.x;
    int tot = 3*P*O;
    if (idx >= tot) return;
    int row = idx / O, o = idx % O;
    int k = row / P, p = row % P;
    float v;
    if (k == 0) v = W[idx] + KAPPA_*(W[(P+p)*O + o] + W[(2*P+p)*O + o]);
    else        v = (1.f - KAPPA_)*W[idx];
    Wf[idx] = v;
}

// time-covariate MLP (Linear 60->10, Linear 10->1600), one block per row
__global__ void mlp_kernel(const float* __restrict__ Tin,
                           const float* __restrict__ W1, const float* __restrict__ b1,
                           const float* __restrict__ W2, const float* __restrict__ b2,
                           int dsel) {
    float* out = dsel ? g_EMBY : g_EMBX;
    int r = blockIdx.x, tid = threadIdx.x;
    __shared__ float tin[60];
    __shared__ float hid[10];
    if (tid < 60) tin[tid] = Tin[(long)r*60 + tid];
    __syncthreads();
    if (tid < 10) {
        float s = b1[tid];
        for (int i = 0; i < 60; i++) s += tin[i]*W1[i*10 + tid];
        hid[tid] = s;
    }
    __syncthreads();
    for (int o = tid; o < N_*TC_H; o += 256) {
        float s = b2[o];
        #pragma unroll
        for (int j = 0; j < 10; j++) s += hid[j]*W2[j*(N_*TC_H) + o];
        out[(long)r*(N_*TC_H) + o] = s;
    }
}

__global__ void zero_state() {
    int i = blockIdx.x*256 + threadIdx.x;
    if (i < NB*H_) { g_H0[i] = 0.f; g_H1[i] = 0.f; }
    if (i < NB*CIN_) g_GO[i] = 0.f;
}

// Build slice0 of g_F for layer 0: [x(2) | t-emb(2) | h0(64)], CF=204
__global__ void build_xh0(const float* __restrict__ xs, int t, int isDec) {
    int idx = blockIdx.x*256 + threadIdx.x;
    if (idx >= NB*68) return;
    int c = idx % 68, row = idx / 68;
    int b = row % B_, n = row / B_;
    float v;
    if (isDec) {
        if (c < 2)      v = g_GO[row*2 + c];
        else if (c < 4) v = g_EMBY[(long)(b*HOR_ + t)*(N_*TC_H) + n*TC_H + (c-2)];
        else            v = g_H0[(long)row*64 + (c-4)];
    } else {
        if (c < 2)      v = xs[((long)(b*T_ + t)*N_ + n)*CIN_ + c];
        else if (c < 4) v = g_EMBX[(long)(b*T_ + t)*(N_*TC_H) + n*TC_H + (c-2)];
        else            v = g_H0[(long)row*64 + (c-4)];
    }
    g_F[(long)row*204 + c] = v;
}

// Build slice0 of g_F for layer 1: [h0(64) | h1(64)], CF=384
__global__ void build_xh1() {
    int idx = blockIdx.x*256 + threadIdx.x;
    if (idx >= NB*128) return;
    int c = idx % 128, row = idx / 128;
    float v = (c < 64) ? g_H0[(long)row*64 + c] : g_H1[(long)row*64 + (c-64)];
    g_F[(long)row*384 + c] = v;
}

// Candidate buffer: slice0 = [x | r*h]; copy Y1x/Y2x prefixes from g_F
__global__ void build_fc(int Px, int P1, int CF, int hsel) {
    int per = P1 + 2*Px;
    int idx = blockIdx.x*256 + threadIdx.x;
    if (idx >= NB*per) return;
    int j = idx % per, row = idx / per;
    const float* Hb = hsel ? g_H1 : g_H0;
    long base = (long)row*CF;
    if (j < P1) {
        float v;
        if (j < Px) v = g_F[base + j];
        else {
            int c = j - Px;
            float r = g_UR[(long)row*128 + 64 + c];
            v = r * Hb[(long)row*64 + c];
        }
        g_FC[base + j] = v;
    } else {
        int j2 = j - P1;
        int k = j2 / Px, c = j2 - k*Px;
        int off = (k+1)*P1 + c;
        g_FC[base + off] = g_F[base + off];
    }
}

// ---------------- graph propagation GEMM ----------------
// out[n,(b,c)] = sum_m GT[n,m] * buf[m,(b,c)] over sub-slice columns.
// Layout: elem (node, b, c) at (node*B + b)*CF + c.
// res_off >= 0: out = 2*acc - buf[...res_off...]  (Chebyshev T2 recurrence)
__global__ void __launch_bounds__(256) prop_gemm(int bufSel, int CF, int src_off,
                                                 int dst_off, int res_off, int Psub) {
    float* buf = bufSel ? g_FC : g_F;
    __shared__ __align__(16) float As[8][128];
    __shared__ __align__(16) float Bs[8][128];
    int tid = threadIdx.x;
    int n0 = blockIdx.y * 128;
    int j0 = blockIdx.x * 128;
    int tr = (tid >> 4) * 8;
    int tc = (tid & 15) * 8;
    float acc[8][8];
    #pragma unroll
    for (int i = 0; i < 8; i++)
        #pragma unroll
        for (int j = 0; j < 8; j++) acc[i][j] = 0.f;

    int ar = tid >> 1, ac = (tid & 1)*4;       // A tile load: 1 float4/thread
    int jl = tid & 127, kb = (tid >> 7) * 4;   // B tile load: 4 scalars/thread
    int jg = j0 + jl;
    int bidx = jg / Psub;
    int cidx = jg - bidx*Psub;
    long rowStride = (long)B_*CF;
    long srcCol = (long)bidx*CF + src_off + cidx;

    for (int k0 = 0; k0 < N_; k0 += 8) {
        int nn = n0 + ar;
        float4 v = make_float4(0.f,0.f,0.f,0.f);
        if (nn < N_) v = *(const float4*)(g_GT + (long)nn*N_ + k0 + ac);
        As[ac+0][ar] = v.x; As[ac+1][ar] = v.y; As[ac+2][ar] = v.z; As[ac+3][ar] = v.w;
        #pragma unroll
        for (int u = 0; u < 4; u++) {
            int kk = kb + u;
            Bs[kk][jl] = buf[(long)(k0+kk)*rowStride + srcCol];
        }
        __syncthreads();
        #pragma unroll
        for (int kk = 0; kk < 8; kk++) {
            float a[8], bv[8];
            *(float4*)(a)    = *(const float4*)&As[kk][tr];
            *(float4*)(a+4)  = *(const float4*)&As[kk][tr+4];
            *(float4*)(bv)   = *(const float4*)&Bs[kk][tc];
            *(float4*)(bv+4) = *(const float4*)&Bs[kk][tc+4];
            #pragma unroll
            for (int i = 0; i < 8; i++)
                #pragma unroll
                for (int j = 0; j < 8; j++) acc[i][j] += a[i]*bv[j];
        }
        __syncthreads();
    }
    #pragma unroll
    for (int j = 0; j < 8; j++) {
        int jo = j0 + tc + j;
        int bo = jo / Psub;
        int co = jo - bo*Psub;
        long cdst = (long)bo*CF + dst_off + co;
        long cres = (res_off >= 0) ? ((long)bo*CF + res_off + co) : 0;
        #pragma unroll
        for (int i = 0; i < 8; i++) {
            int nn = n0 + tr + i;
            if (nn < N_) {
                long base = (long)nn*rowStride;
                float v = acc[i][j];
                if (res_off >= 0) v = 2.f*v - buf[base + cres];
                buf[base + cdst] = v;
            }
        }
    }
}

// ---------------- projection GEMM (dense, K = 3*P1, with fused epilogues) ----
// MODE 0: gate -> UR = sigmoid(acc + bias)          (NO = 128)
// MODE 1: cand -> H  = (1-u)*h + u*tanh(acc + bias) (NO = 64)
template<int NO, int MODE>
__global__ void __launch_bounds__(256) proj_gemm(int bufSel, int lda, int Kdim,
                                                 int wsel, const float* __restrict__ bias,
                                                 int hsel) {
    const float* A = bufSel ? g_FC : g_F;
    const float* W = (MODE == 0) ? g_WG[wsel] : g_WC[wsel];
    constexpr int TN = NO/16;
    __shared__ __align__(16) float As[8][128];
    __shared__ __align__(16) float Ws[8][NO];
    int tid = threadIdx.x;
    long row0 = (long)blockIdx.x * 128;
    int tr = (tid >> 4) * 8;
    int tc = (tid & 15) * TN;
    float acc[8][TN];
    #pragma unroll
    for (int i = 0; i < 8; i++)
        #pragma unroll
        for (int j = 0; j < TN; j++) acc[i][j] = 0.f;

    int r = tid >> 1, kbase = (tid & 1)*4;
    const float* arow = A + (row0 + r)*lda;

    for (int k0 = 0; k0 < Kdim; k0 += 8) {
        #pragma unroll
        for (int u = 0; u < 4; u++) {
            int kk = kbase + u, kg = k0 + kk;
            As[kk][r] = (kg < Kdim) ? arow[kg] : 0.f;
        }
        #pragma unroll
        for (int e = tid; e < 8*NO; e += 256) {
            int kk = e / NO, c = e % NO, kg = k0 + kk;
            Ws[kk][c] = (kg < Kdim) ? W[(long)kg*NO + c] : 0.f;
        }
        __syncthreads();
        #pragma unroll
        for (int kk = 0; kk < 8; kk++) {
            float a[8], bv[TN];
            *(float4*)(a)   = *(const float4*)&As[kk][tr];
            *(float4*)(a+4) = *(const float4*)&As[kk][tr+4];
            #pragma unroll
            for (int j = 0; j < TN; j += 4) *(float4*)(bv+j) = *(const float4*)&Ws[kk][tc+j];
            #pragma unroll
            for (int i = 0; i < 8; i++)
                #pragma unroll
                for (int j = 0; j < TN; j++) acc[i][j] += a[i]*bv[j];
        }
        __syncthreads();
    }
    #pragma unroll
    for (int i = 0; i < 8; i++) {
        long row = row0 + tr + i;
        #pragma unroll
        for (int j = 0; j < TN; j++) {
            int c = tc + j;
            float v = acc[i][j] + bias[c];
            if (MODE == 0) {
                g_UR[row*128 + c] = 1.f/(1.f + expf(-v));
            } else {
                float cv = tanhf(v);
                float u = g_UR[row*128 + c];           // u = first 64 cols of UR
                float* Hb = hsel ? g_H1 : g_H0;
                float h = Hb[row*64 + c];
                Hb[row*64 + c] = (1.f - u)*h + u*cv;
            }
        }
    }
}

// ---------------- decoder memory attention + output projection ----------------
__global__ void query_kernel(const float* __restrict__ Wa) {
    int b = blockIdx.x, tid = threadIdx.x;
    float p[8];
    #pragma unroll
    for (int d = 0; d < 8; d++) p[d] = 0.f;
    for (int idx = tid; idx < N_*H_; idx += 256) {
        int n = idx >> 6, j = idx & 63;
        float v = g_H1[(long)(n*B_ + b)*64 + j];
        const float* w = Wa + (long)idx*8;
        #pragma unroll
        for (int d = 0; d < 8; d++) p[d] += v*w[d];
    }
    #pragma unroll
    for (int d = 0; d < 8; d++)
        for (int off = 16; off > 0; off >>= 1) p[d] += __shfl_down_sync(0xffffffffu, p[d], off);
    __shared__ float sm[8][8];
    int w = tid >> 5, l = tid & 31;
    if (l == 0) { for (int d = 0; d < 8; d++) sm[w][d] = p[d]; }
    __syncthreads();
    if (tid < 8) {
        float s = 0.f;
        for (int ww = 0; ww < 8; ww++) s += sm[ww][tid];
        g_Q[b*8 + tid] = s;
    }
}

__global__ void attm_kernel(const float* __restrict__ mem, const float* __restrict__ fcw) {
    int b = blockIdx.x, tid = threadIdx.x;
    __shared__ float am[8];
    if (tid == 0) {
        float q[8];
        for (int d = 0; d < 8; d++) q[d] = g_Q[b*8 + d];
        float s[4]; float mx = -1e30f;
        for (int m = 0; m < 4; m++) {
            float a = 0.f;
            for (int d = 0; d < 8; d++) a += q[d]*mem[m*8 + d];
            s[m] = a; mx = fmaxf(mx, a);
        }
        float den = 0.f;
        for (int m = 0; m < 4; m++) { s[m] = expf(s[m]-mx); den += s[m]; }
        for (int d = 0; d < 8; d++) {
            float a = 0.f;
            for (int m = 0; m < 4; m++) a += (s[m]/den)*mem[m*8 + d];
            am[d] = a;
        }
    }
    __syncthreads();
    for (int i = tid; i < N_*MDIM_; i += 256) {
        float s = 0.f;
        #pragma unroll
        for (int d = 0; d < 8; d++) s += am[d]*fcw[(long)d*(N_*MDIM_) + i];
        g_ATTM[(long)b*(N_*MDIM_) + i] = s;
    }
}

__global__ void out_kernel(const float* __restrict__ pW, const float* __restrict__ pb,
                           float* __restrict__ outp, int s) {
    int row = blockIdx.x*256 + threadIdx.x;
    if (row >= NB) return;
    int b = row % B_, n = row / B_;
    float a0 = pb[0], a1 = pb[1];
    const float* h = g_H1 + (long)row*64;
    #pragma unroll
    for (int j = 0; j < 64; j++) { float v = h[j]; a0 += v*pW[j*2]; a1 += v*pW[j*2+1]; }
    const float* at = g_ATTM + (long)b*(N_*MDIM_) + n*8;
    #pragma unroll
    for (int d = 0; d < 8; d++) { float v = at[d]; a0 += v*pW[(64+d)*2]; a1 += v*pW[(64+d)*2+1]; }
    a0 = fmaxf(a0, 0.f); a1 = fmaxf(a1, 0.f);
    g_GO[row*2] = a0; g_GO[row*2+1] = a1;
    long o = ((long)(b*HOR_ + s)*N_ + n)*CIN_;
    outp[o] = a0; outp[o+1] = a1;
}

// ---------------- orchestration ----------------
extern "C" void kernel_launch(void* const* d_in, const int* in_sizes, int n_in,
                              void* d_out, int out_size) {
    (void)in_sizes; (void)n_in; (void)out_size;
    const float* x_seq = (const float*)d_in[0];
    const float* t_x   = (const float*)d_in[1];
    const float* t_y   = (const float*)d_in[2];
    const float* G     = (const float*)d_in[3];
    const float* eWg0  = (const float*)d_in[4];  const float* ebg0 = (const float*)d_in[5];
    const float* eWc0  = (const float*)d_in[6];  const float* ebc0 = (const float*)d_in[7];
    const float* eWg1  = (const float*)d_in[8];  const float* ebg1 = (const float*)d_in[9];
    const float* eWc1  = (const float*)d_in[10]; const float* ebc1 = (const float*)d_in[11];
    const float* dWg0  = (const float*)d_in[12]; const float* dbg0 = (const float*)d_in[13];
    const float* dWc0  = (const float*)d_in[14]; const float* dbc0 = (const float*)d_in[15];
    const float* dWg1  = (const float*)d_in[16]; const float* dbg1 = (const float*)d_in[17];
    const float* dWc1  = (const float*)d_in[18]; const float* dbc1 = (const float*)d_in[19];
    const float* mW1   = (const float*)d_in[20]; const float* mb1  = (const float*)d_in[21];
    const float* mW2   = (const float*)d_in[22]; const float* mb2  = (const float*)d_in[23];
    const float* mem   = (const float*)d_in[24];
    const float* Wa    = (const float*)d_in[25];
    const float* fcw   = (const float*)d_in[26];
    const float* projW = (const float*)d_in[27];
    const float* projb = (const float*)d_in[28];
    float* outp = (float*)d_out;

    transpose_kernel<<<dim3(25,25), dim3(32,32)>>>(G);

    auto fold = [](const float* W, int isGate, int widx, int P, int O) {
        int tot = 3*P*O;
        fold_kernel<<<(tot+255)/256, 256>>>(W, isGate, widx, P, O);
    };
    fold(eWg0,1,0,68,128);  fold(eWc0,0,0,68,64);
    fold(eWg1,1,1,128,128); fold(eWc1,0,1,128,64);
    fold(dWg0,1,2,68,128);  fold(dWc0,0,2,68,64);
    fold(dWg1,1,3,128,128); fold(dWc1,0,3,128,64);

    mlp_kernel<<<B_*T_,   256>>>(t_x, mW1, mb1, mW2, mb2, 0);
    mlp_kernel<<<B_*HOR_, 256>>>(t_y, mW1, mb1, mW2, mb2, 1);
    zero_state<<<(NB*H_+255)/256, 256>>>();

    auto cell = [&](int layer, int wsel, const float* bg, const float* bc) {
        int P1 = layer ? 128 : 68;
        int Px = layer ? 64 : 4;
        int CF = 3*P1;
        // propagate [x|h]:  Y1 = G^T X ;  Y2 = 2 G^T Y1 - X
        prop_gemm<<<dim3(B_*P1/128, 7), 256>>>(0, CF, 0,  P1,   -1, P1);
        prop_gemm<<<dim3(B_*P1/128, 7), 256>>>(0, CF, P1, 2*P1,  0, P1);
        // gate: UR = sigmoid([X|Y1|Y2] @ Wg' + bg)
        proj_gemm<128,0><<<NB/128, 256>>>(0, CF, 3*P1, wsel, bg, layer);
        // candidate features: slice0=[x|r*h], copy x-prefixes of Y1/Y2
        int nfc = NB*(P1 + 2*Px);
        build_fc<<<(nfc+255)/256, 256>>>(Px, P1, CF, layer);
        // propagate r*h (width 64)
        prop_gemm<<<dim3(B_*64/128, 7), 256>>>(1, CF, Px,      P1+Px,   -1, 64);
        prop_gemm<<<dim3(B_*64/128, 7), 256>>>(1, CF, P1+Px,   2*P1+Px, Px, 64);
        // candidate + GRU update (fused): h = (1-u)h + u*tanh(...)
        proj_gemm<64,1><<<NB/128, 256>>>(1, CF, 3*P1, wsel, bc, layer);
    };

    // encoder (layers interleaved per timestep — equivalent to layer-wise scan)
    for (int t = 0; t < T_; t++) {
        build_xh0<<<(NB*68+255)/256, 256>>>(x_seq, t, 0);
        cell(0, 0, ebg0, ebc0);
        build_xh1<<<(NB*128+255)/256, 256>>>();
        cell(1, 1, ebg1, ebc1);
    }
    // decoder (autoregressive)
    for (int s = 0; s < HOR_; s++) {
        build_xh0<<<(NB*68+255)/256, 256>>>(x_seq, s, 1);
        cell(0, 2, dbg0, dbc0);
        build_xh1<<<(NB*128+255)/256, 256>>>();
        cell(1, 3, dbg1, dbc1);
        query_kernel<<<B_, 256>>>(Wa);
        attm_kernel<<<B_, 256>>>(mem, fcw);
        out_kernel<<<NB/256, 256>>>(projW, projb, outp, s);
    }
}

// round 3
// speedup vs baseline: 1.3443x; 1.3443x over previous
#include <cuda_runtime.h>
#include <math.h>

#define B_    64
#define T_    12
#define N_    800
#define CIN_  2
#define H_    64
#define HOR_  12
#define TC_H  2
#define KAPPA_ 0.05f
#define NB    (N_*B_)      /* 51200 rows (node-major, batch inner) */

// ---------------- scratch (device globals; no allocs allowed) ----------------
__device__ float g_A2[1600*800];              // rows 0..799: G^T ; 800..1599: 2 G^T G^T - I
__device__ float g_EMBX[B_*T_*N_*TC_H];
__device__ float g_EMBY[B_*HOR_*N_*TC_H];
__device__ float g_H0[NB*H_];
__device__ float g_H1[NB*H_];
__device__ float g_F [NB*384];                // gate features [X|Y1|Y2]
__device__ float g_FC[NB*384];                // candidate features
__device__ float g_UR[NB*128];                // sigmoid(u|r)
__device__ float g_GO[NB*CIN_];
__device__ float g_Q [B_*8];
__device__ float g_ATTM[B_*N_*8];
__device__ float g_WG[4][384*128];            // folded gate weights
__device__ float g_WC[4][384*64];             // folded candidate weights

// ---------------- setup kernels ----------------
__global__ void transpose_kernel(const float* __restrict__ G) {
    __shared__ float t[32][33];
    int x = blockIdx.x*32 + threadIdx.x, y = blockIdx.y*32 + threadIdx.y;
    t[threadIdx.y][threadIdx.x] = G[y*N_ + x];
    __syncthreads();
    int x2 = blockIdx.y*32 + threadIdx.x, y2 = blockIdx.x*32 + threadIdx.y;
    g_A2[y2*N_ + x2] = t[threadIdx.x][threadIdx.y];
}

// G2 = 2 * GT @ GT - I   (written into g_A2 rows 800..1599)
__global__ void __launch_bounds__(256) g2_kernel() {
    __shared__ float As[8][128], Bs[8][128];
    int tid = threadIdx.x;
    int i0 = blockIdx.y*128, j0 = blockIdx.x*128;
    int ty = tid>>4, tx = tid&15, rl = ty*4, cl = tx*4;
    int ar = tid>>1, ac = (tid&1)*4;
    int bk = tid>>5, bj = (tid&31)*4;
    float acc[8][8];
    #pragma unroll
    for (int i=0;i<8;i++) {
        #pragma unroll
        for (int j=0;j<8;j++) acc[i][j]=0.f;
    }
    for (int k0=0;k0<N_;k0+=8) {
        float4 av = make_float4(0,0,0,0);
        if (i0+ar < N_) av = *(const float4*)&g_A2[(long)(i0+ar)*N_ + k0+ac];
        As[ac+0][ar]=av.x; As[ac+1][ar]=av.y; As[ac+2][ar]=av.z; As[ac+3][ar]=av.w;
        float4 bv = make_float4(0,0,0,0);
        if (j0+bj < N_) bv = *(const float4*)&g_A2[(long)(k0+bk)*N_ + j0+bj];
        *(float4*)&Bs[bk][bj] = bv;
        __syncthreads();
        #pragma unroll
        for (int kk=0;kk<8;kk++) {
            float a[8], b[8];
            *(float4*)a     = *(const float4*)&As[kk][rl];
            *(float4*)(a+4) = *(const float4*)&As[kk][rl+64];
            *(float4*)b     = *(const float4*)&Bs[kk][cl];
            *(float4*)(b+4) = *(const float4*)&Bs[kk][cl+64];
            #pragma unroll
            for (int i=0;i<8;i++) {
                #pragma unroll
                for (int j=0;j<8;j++) acc[i][j] += a[i]*b[j];
            }
        }
        __syncthreads();
    }
    #pragma unroll
    for (int i=0;i<8;i++) {
        int r = i0 + (i<4 ? rl+i : 64+rl+i-4);
        if (r >= N_) continue;
        #pragma unroll
        for (int j=0;j<8;j++) {
            int c = j0 + (j<4 ? cl+j : 64+cl+j-4);
            if (c >= N_) continue;
            g_A2[(long)(N_+r)*N_ + c] = 2.f*acc[i][j] - (r==c ? 1.f : 0.f);
        }
    }
}

__global__ void fold_kernel(const float* __restrict__ W, int isGate, int widx, int P, int O) {
    float* Wf = isGate ? g_WG[widx] : g_WC[widx];
    int idx = blockIdx.x*256 + threadIdx.x;
    int tot = 3*P*O;
    if (idx >= tot) return;
    int row = idx / O, o = idx % O;
    int k = row / P, p = row % P;
    float v;
    if (k == 0) v = W[idx] + KAPPA_*(W[(P+p)*O + o] + W[(2*P+p)*O + o]);
    else        v = (1.f - KAPPA_)*W[idx];
    Wf[idx] = v;
}

__global__ void mlp_kernel(const float* __restrict__ Tin,
                           const float* __restrict__ W1, const float* __restrict__ b1,
                           const float* __restrict__ W2, const float* __restrict__ b2,
                           int dsel) {
    float* out = dsel ? g_EMBY : g_EMBX;
    int r = blockIdx.x, tid = threadIdx.x;
    __shared__ float tin[60];
    __shared__ float hid[10];
    if (tid < 60) tin[tid] = Tin[(long)r*60 + tid];
    __syncthreads();
    if (tid < 10) {
        float s = b1[tid];
        for (int i = 0; i < 60; i++) s += tin[i]*W1[i*10 + tid];
        hid[tid] = s;
    }
    __syncthreads();
    for (int o = tid; o < N_*TC_H; o += 256) {
        float s = b2[o];
        #pragma unroll
        for (int j = 0; j < 10; j++) s += hid[j]*W2[j*(N_*TC_H) + o];
        out[(long)r*(N_*TC_H) + o] = s;
    }
}

__global__ void zero_state() {
    int i = blockIdx.x*256 + threadIdx.x;
    if (i < NB*H_) { g_H0[i] = 0.f; g_H1[i] = 0.f; }
    if (i < NB*CIN_) g_GO[i] = 0.f;
}

// ---------------- feature builders ----------------
__global__ void build_xh0(const float* __restrict__ xs, int t, int isDec) {
    int idx = blockIdx.x*256 + threadIdx.x;
    if (idx >= NB*68) return;
    int c = idx % 68, row = idx / 68;
    int b = row % B_, n = row / B_;
    float v;
    if (isDec) {
        if (c < 2)      v = g_GO[row*2 + c];
        else if (c < 4) v = g_EMBY[(long)(b*HOR_ + t)*(N_*TC_H) + n*TC_H + (c-2)];
        else            v = g_H0[(long)row*64 + (c-4)];
    } else {
        if (c < 2)      v = xs[((long)(b*T_ + t)*N_ + n)*CIN_ + c];
        else if (c < 4) v = g_EMBX[(long)(b*T_ + t)*(N_*TC_H) + n*TC_H + (c-2)];
        else            v = g_H0[(long)row*64 + (c-4)];
    }
    g_F[(long)row*204 + c] = v;
}

__global__ void build_xh1() {
    int idx = blockIdx.x*256 + threadIdx.x;
    if (idx >= NB*128) return;
    int c = idx % 128, row = idx / 128;
    float v = (c < 64) ? g_H0[(long)row*64 + c] : g_H1[(long)row*64 + (c-64)];
    g_F[(long)row*384 + c] = v;
}

// layer0 candidate: FC slice0 = [x(4) | r*h(64)]; copy tiny x-prefixes of Y1/Y2
__global__ void build_fc0() {
    int idx = blockIdx.x*256 + threadIdx.x;
    if (idx >= NB*76) return;
    int j = idx % 76, row = idx / 76;
    long base = (long)row*204;
    if (j < 4)       g_FC[base + j] = g_F[base + j];
    else if (j < 68) { int c = j-4; g_FC[base + j] = g_UR[(long)row*128 + 64 + c]*g_H0[(long)row*64 + c]; }
    else if (j < 72) { int c = 68 + (j-68);  g_FC[base + c] = g_F[base + c]; }
    else             { int c = 136 + (j-72); g_FC[base + c] = g_F[base + c]; }
}

// layer1 candidate: only materialize r*h1 at FC cols [64,128); x-parts read from g_F via parity
__global__ void build_rh1() {
    int idx = blockIdx.x*256 + threadIdx.x;
    if (idx >= NB*64) return;
    int c = idx & 63, row = idx >> 6;
    g_FC[(long)row*384 + 64 + c] = g_UR[(long)row*128 + 64 + c]*g_H1[(long)row*64 + c];
}

// ---------------- stacked graph propagation: [Y1;Y2] = [GT;G2] @ X -------------
// buf columns: global col j -> batch b=j/Psub, chan c=j%Psub at (b*CF + src_off + c)
// row m at m*rowStride.  Output row i<800 -> slice d1, i>=800 -> slice d2.
__global__ void __launch_bounds__(256,2) prop2(int bufSel, int CF, int src_off,
                                               int d1, int d2, int Psub) {
    float* buf = bufSel ? g_FC : g_F;
    __shared__ float As[2][8][128];
    __shared__ float Bs[2][8][128];
    int tid = threadIdx.x;
    int n0 = blockIdx.y*128, j0 = blockIdx.x*128;
    int ty = tid>>4, tx = tid&15, rl = ty*4, cl = tx*4;
    int ar = tid>>1, ac = (tid&1)*4;
    int bk = tid>>5, bj = (tid&31)*4;
    int jg = j0 + bj;
    int bo = jg / Psub, co = jg - bo*Psub;
    long rowStride = (long)B_*CF;
    long bcol = (long)bo*CF + src_off + co;
    int arow = n0 + ar;
    bool aval = arow < 1600;

    float acc[8][8];
    #pragma unroll
    for (int i=0;i<8;i++) {
        #pragma unroll
        for (int j=0;j<8;j++) acc[i][j]=0.f;
    }

    // prologue: panel 0
    float4 av = aval ? *(const float4*)&g_A2[(long)arow*N_ + ac] : make_float4(0,0,0,0);
    As[0][ac+0][ar]=av.x; As[0][ac+1][ar]=av.y; As[0][ac+2][ar]=av.z; As[0][ac+3][ar]=av.w;
    *(float4*)&Bs[0][bk][bj] = *(const float4*)&buf[(long)bk*rowStride + bcol];
    __syncthreads();

    int cur = 0;
    for (int k0 = 8; k0 <= N_; k0 += 8) {
        float4 av2, bv2;
        bool more = k0 < N_;
        if (more) {
            av2 = aval ? *(const float4*)&g_A2[(long)arow*N_ + k0 + ac] : make_float4(0,0,0,0);
            bv2 = *(const float4*)&buf[(long)(k0+bk)*rowStride + bcol];
        }
        #pragma unroll
        for (int kk=0;kk<8;kk++) {
            float a[8], b[8];
            *(float4*)a     = *(const float4*)&As[cur][kk][rl];
            *(float4*)(a+4) = *(const float4*)&As[cur][kk][rl+64];
            *(float4*)b     = *(const float4*)&Bs[cur][kk][cl];
            *(float4*)(b+4) = *(const float4*)&Bs[cur][kk][cl+64];
            #pragma unroll
            for (int i=0;i<8;i++) {
                #pragma unroll
                for (int j=0;j<8;j++) acc[i][j] += a[i]*b[j];
            }
        }
        if (more) {
            int nxt = cur^1;
            As[nxt][ac+0][ar]=av2.x; As[nxt][ac+1][ar]=av2.y;
            As[nxt][ac+2][ar]=av2.z; As[nxt][ac+3][ar]=av2.w;
            *(float4*)&Bs[nxt][bk][bj] = bv2;
            __syncthreads();
            cur = nxt;
        }
    }

    // epilogue: float4 stores into Y slices
    int cAg = j0 + cl, cBg = j0 + cl + 64;
    int boA = cAg/Psub, coA = cAg - boA*Psub;
    int boB = cBg/Psub, coB = cBg - boB*Psub;
    long colA = (long)boA*CF + coA;
    long colB = (long)boB*CF + coB;
    #pragma unroll
    for (int i=0;i<8;i++) {
        int r = n0 + (i<4 ? rl+i : 64+rl+i-4);
        if (r >= 1600) continue;
        long base = (r < 800) ? ((long)r*rowStride + d1) : ((long)(r-800)*rowStride + d2);
        float4 v0 = make_float4(acc[i][0],acc[i][1],acc[i][2],acc[i][3]);
        float4 v1 = make_float4(acc[i][4],acc[i][5],acc[i][6],acc[i][7]);
        *(float4*)&buf[base + colA] = v0;
        *(float4*)&buf[base + colB] = v1;
    }
}

// ---------------- projection GEMM with fused GRU epilogues ----------------
// MODE 0: UR = sigmoid(F @ Wg + bg)   NO=128
// MODE 1: H  = (1-u)h + u*tanh(A @ Wc + bc)  NO=64
// srcMode: 0 = g_F, 1 = g_FC, 2 = parity (k>>6 even -> g_F, odd -> g_FC)
template<int NO, int MODE>
__global__ void __launch_bounds__(256,2) proj2(int srcMode, int CF, int Kdim, int wsel,
                                               const float* __restrict__ bias, int hsel) {
    const float* W = (MODE==0) ? g_WG[wsel] : g_WC[wsel];
    constexpr int TN = (NO==128) ? 8 : 4;
    __shared__ float As[2][8][128];
    __shared__ float Ws[2][8][NO];
    int tid = threadIdx.x;
    long row0 = (long)blockIdx.x*128;
    int ty = tid>>4, tx = tid&15, rl = ty*4, cl = tx*4;
    int ar = tid>>1, ac = (tid&1)*4;
    int wk, wc; bool wact;
    if (NO==128) { wk = tid>>5; wc = (tid&31)*4; wact = true; }
    else         { wk = tid>>4; wc = (tid&15)*4; wact = (tid < 128); }

    float acc[8][TN];
    #pragma unroll
    for (int i=0;i<8;i++) {
        #pragma unroll
        for (int j=0;j<TN;j++) acc[i][j]=0.f;
    }

    auto loadA = [&](int k0) -> float4 {
        int kg = k0 + ac;
        if (kg >= Kdim) return make_float4(0,0,0,0);
        const float* Ab;
        if (srcMode == 0) Ab = g_F;
        else if (srcMode == 1) Ab = g_FC;
        else Ab = ((kg>>6)&1) ? g_FC : g_F;
        return *(const float4*)&Ab[(row0+ar)*CF + kg];
    };
    auto loadW = [&](int k0) -> float4 {
        int kg = k0 + wk;
        if (!wact || kg >= Kdim) return make_float4(0,0,0,0);
        return *(const float4*)&W[(long)kg*NO + wc];
    };

    int KT = ((Kdim + 7)/8)*8;
    float4 av = loadA(0), wv = loadW(0);
    As[0][ac+0][ar]=av.x; As[0][ac+1][ar]=av.y; As[0][ac+2][ar]=av.z; As[0][ac+3][ar]=av.w;
    if (wact) *(float4*)&Ws[0][wk][wc] = wv;
    __syncthreads();

    int cur = 0;
    for (int k0 = 8; k0 <= KT; k0 += 8) {
        float4 av2, wv2;
        bool more = k0 < KT;
        if (more) { av2 = loadA(k0); wv2 = loadW(k0); }
        #pragma unroll
        for (int kk=0;kk<8;kk++) {
            float a[8], b[TN];
            *(float4*)a     = *(const float4*)&As[cur][kk][rl];
            *(float4*)(a+4) = *(const float4*)&As[cur][kk][rl+64];
            *(float4*)b = *(const float4*)&Ws[cur][kk][cl];
            if (NO==128) *(float4*)(b+4) = *(const float4*)&Ws[cur][kk][cl+64];
            #pragma unroll
            for (int i=0;i<8;i++) {
                #pragma unroll
                for (int j=0;j<TN;j++) acc[i][j] += a[i]*b[j];
            }
        }
        if (more) {
            int nxt = cur^1;
            As[nxt][ac+0][ar]=av2.x; As[nxt][ac+1][ar]=av2.y;
            As[nxt][ac+2][ar]=av2.z; As[nxt][ac+3][ar]=av2.w;
            if (wact) *(float4*)&Ws[nxt][wk][wc] = wv2;
            __syncthreads();
            cur = nxt;
        }
    }

    float* Hb = hsel ? g_H1 : g_H0;
    #pragma unroll
    for (int i=0;i<8;i++) {
        long row = row0 + (i<4 ? rl+i : 64+rl+i-4);
        #pragma unroll
        for (int j=0;j<TN;j++) {
            int c = (NO==128) ? ((j<4) ? cl+j : 64+cl+j-4) : (cl+j);
            float v = acc[i][j] + bias[c];
            if (MODE == 0) {
                g_UR[row*128 + c] = 1.f/(1.f + expf(-v));
            } else {
                float cv = tanhf(v);
                float u  = g_UR[row*128 + c];
                float h  = Hb[row*64 + c];
                Hb[row*64 + c] = (1.f - u)*h + u*cv;
            }
        }
    }
}

// ---------------- decoder memory attention + output projection ----------------
__global__ void query_kernel(const float* __restrict__ Wa) {
    int b = blockIdx.x, tid = threadIdx.x;
    float p[8];
    #pragma unroll
    for (int d = 0; d < 8; d++) p[d] = 0.f;
    for (int idx = tid; idx < N_*H_; idx += 256) {
        int n = idx >> 6, j = idx & 63;
        float v = g_H1[(long)(n*B_ + b)*64 + j];
        const float* w = Wa + (long)idx*8;
        #pragma unroll
        for (int d = 0; d < 8; d++) p[d] += v*w[d];
    }
    #pragma unroll
    for (int d = 0; d < 8; d++)
        for (int off = 16; off > 0; off >>= 1) p[d] += __shfl_down_sync(0xffffffffu, p[d], off);
    __shared__ float sm[8][8];
    int w = tid >> 5, l = tid & 31;
    if (l == 0) { for (int d = 0; d < 8; d++) sm[w][d] = p[d]; }
    __syncthreads();
    if (tid < 8) {
        float s = 0.f;
        for (int ww = 0; ww < 8; ww++) s += sm[ww][tid];
        g_Q[b*8 + tid] = s;
    }
}

__global__ void attm_kernel(const float* __restrict__ mem, const float* __restrict__ fcw) {
    int b = blockIdx.x, tid = threadIdx.x;
    __shared__ float am[8];
    if (tid == 0) {
        float q[8];
        for (int d = 0; d < 8; d++) q[d] = g_Q[b*8 + d];
        float s[4]; float mx = -1e30f;
        for (int m = 0; m < 4; m++) {
            float a = 0.f;
            for (int d = 0; d < 8; d++) a += q[d]*mem[m*8 + d];
            s[m] = a; mx = fmaxf(mx, a);
        }
        float den = 0.f;
        for (int m = 0; m < 4; m++) { s[m] = expf(s[m]-mx); den += s[m]; }
        for (int d = 0; d < 8; d++) {
            float a = 0.f;
            for (int m = 0; m < 4; m++) a += (s[m]/den)*mem[m*8 + d];
            am[d] = a;
        }
    }
    __syncthreads();
    for (int i = tid; i < N_*8; i += 256) {
        float s = 0.f;
        #pragma unroll
        for (int d = 0; d < 8; d++) s += am[d]*fcw[(long)d*(N_*8) + i];
        g_ATTM[(long)b*(N_*8) + i] = s;
    }
}

__global__ void out_kernel(const float* __restrict__ pW, const float* __restrict__ pb,
                           float* __restrict__ outp, int s) {
    int row = blockIdx.x*256 + threadIdx.x;
    if (row >= NB) return;
    int b = row % B_, n = row / B_;
    float a0 = pb[0], a1 = pb[1];
    const float* h = g_H1 + (long)row*64;
    #pragma unroll
    for (int j = 0; j < 64; j++) { float v = h[j]; a0 += v*pW[j*2]; a1 += v*pW[j*2+1]; }
    const float* at = g_ATTM + (long)b*(N_*8) + n*8;
    #pragma unroll
    for (int d = 0; d < 8; d++) { float v = at[d]; a0 += v*pW[(64+d)*2]; a1 += v*pW[(64+d)*2+1]; }
    a0 = fmaxf(a0, 0.f); a1 = fmaxf(a1, 0.f);
    g_GO[row*2] = a0; g_GO[row*2+1] = a1;
    long o = ((long)(b*HOR_ + s)*N_ + n)*CIN_;
    outp[o] = a0; outp[o+1] = a1;
}

// ---------------- orchestration ----------------
extern "C" void kernel_launch(void* const* d_in, const int* in_sizes, int n_in,
                              void* d_out, int out_size) {
    (void)in_sizes; (void)n_in; (void)out_size;
    const float* x_seq = (const float*)d_in[0];
    const float* t_x   = (const float*)d_in[1];
    const float* t_y   = (const float*)d_in[2];
    const float* G     = (const float*)d_in[3];
    const float* eWg0  = (const float*)d_in[4];  const float* ebg0 = (const float*)d_in[5];
    const float* eWc0  = (const float*)d_in[6];  const float* ebc0 = (const float*)d_in[7];
    const float* eWg1  = (const float*)d_in[8];  const float* ebg1 = (const float*)d_in[9];
    const float* eWc1  = (const float*)d_in[10]; const float* ebc1 = (const float*)d_in[11];
    const float* dWg0  = (const float*)d_in[12]; const float* dbg0 = (const float*)d_in[13];
    const float* dWc0  = (const float*)d_in[14]; const float* dbc0 = (const float*)d_in[15];
    const float* dWg1  = (const float*)d_in[16]; const float* dbg1 = (const float*)d_in[17];
    const float* dWc1  = (const float*)d_in[18]; const float* dbc1 = (const float*)d_in[19];
    const float* mW1   = (const float*)d_in[20]; const float* mb1  = (const float*)d_in[21];
    const float* mW2   = (const float*)d_in[22]; const float* mb2  = (const float*)d_in[23];
    const float* mem   = (const float*)d_in[24];
    const float* Wa    = (const float*)d_in[25];
    const float* fcw   = (const float*)d_in[26];
    const float* projW = (const float*)d_in[27];
    const float* projb = (const float*)d_in[28];
    float* outp = (float*)d_out;

    transpose_kernel<<<dim3(25,25), dim3(32,32)>>>(G);
    g2_kernel<<<dim3(7,7), 256>>>();

    auto fold = [](const float* W, int isGate, int widx, int P, int O) {
        int tot = 3*P*O;
        fold_kernel<<<(tot+255)/256, 256>>>(W, isGate, widx, P, O);
    };
    fold(eWg0,1,0,68,128);  fold(eWc0,0,0,68,64);
    fold(eWg1,1,1,128,128); fold(eWc1,0,1,128,64);
    fold(dWg0,1,2,68,128);  fold(dWc0,0,2,68,64);
    fold(dWg1,1,3,128,128); fold(dWc1,0,3,128,64);

    mlp_kernel<<<B_*T_,   256>>>(t_x, mW1, mb1, mW2, mb2, 0);
    mlp_kernel<<<B_*HOR_, 256>>>(t_y, mW1, mb1, mW2, mb2, 1);
    zero_state<<<(NB*H_+255)/256, 256>>>();

    auto cell0 = [&](int wsel, const float* bg, const float* bc) {
        // gate: [Y1|Y2] of [x|h] (width 68), then UR
        prop2<<<dim3(34,13), 256>>>(0, 204, 0, 68, 136, 68);
        proj2<128,0><<<NB/128, 256>>>(0, 204, 204, wsel, bg, 0);
        // candidate
        build_fc0<<<(NB*76+255)/256, 256>>>();
        prop2<<<dim3(32,13), 256>>>(1, 204, 4, 72, 140, 64);
        proj2<64,1><<<NB/128, 256>>>(1, 204, 204, wsel, bc, 0);
    };
    auto cell1 = [&](int wsel, const float* bg, const float* bc) {
        prop2<<<dim3(64,13), 256>>>(0, 384, 0, 128, 256, 128);
        proj2<128,0><<<NB/128, 256>>>(0, 384, 384, wsel, bg, 1);
        build_rh1<<<(NB*64+255)/256, 256>>>();
        prop2<<<dim3(32,13), 256>>>(1, 384, 64, 192, 320, 64);
        proj2<64,1><<<NB/128, 256>>>(2, 384, 384, wsel, bc, 1);
    };

    // encoder
    for (int t = 0; t < T_; t++) {
        build_xh0<<<(NB*68+255)/256, 256>>>(x_seq, t, 0);
        cell0(0, ebg0, ebc0);
        build_xh1<<<(NB*128+255)/256, 256>>>();
        cell1(1, ebg1, ebc1);
    }
    // decoder
    for (int s = 0; s < HOR_; s++) {
        build_xh0<<<(NB*68+255)/256, 256>>>(x_seq, s, 1);
        cell0(2, dbg0, dbc0);
        build_xh1<<<(NB*128+255)/256, 256>>>();
        cell1(3, dbg1, dbc1);
        query_kernel<<<B_, 256>>>(Wa);
        attm_kernel<<<B_, 256>>>(mem, fcw);
        out_kernel<<<NB/256, 256>>>(projW, projb, outp, s);
    }
}